// round 2
// baseline (speedup 1.0000x reference)
#include <cuda_runtime.h>
#include <math.h>

#define DM 1024      // d_model
#define DI 2048      // d_inner
#define DS 16        // d_state
#define DR 64        // dt_rank
#define BB 2         // batch
#define LL 1024      // seq len
#define MT 2048      // BB*LL (token count)
#define DBCW 96      // dt_rank + 2*d_state

// ---- scratch (static device allocations; no runtime alloc) ----
__device__ float g_xz[(size_t)MT * 2 * DI];     // in_proj output [MT, 4096]
__device__ float g_xs[(size_t)MT * DI];         // conv+silu output [MT, 2048]
__device__ float g_dbc[(size_t)MT * DBCW];      // x_proj output [MT, 96]
__device__ float g_delta[(size_t)MT * DI];      // softplus(dt) [MT, 2048]
__device__ float g_y[(size_t)MT * DI];          // scan output (pre out_proj)

__device__ __forceinline__ float softplusf(float x) {
    return (x > 20.f) ? x : log1pf(expf(x));
}

// ============================================================================
// Tiled fp32 GEMM: C[M,N] = A[M,K] * B[N,K]^T  (both row-major, K contiguous)
// 128x128 block tile, BK=16, 256 threads, 8x8 per-thread micro-tile.
// Requires M%128==0, N%128==0, K%16==0, lda/ldb row starts 16B-aligned.
// EPI==1: fused  C = softplus(C + bias[n])
// ============================================================================
template<int EPI>
__global__ __launch_bounds__(256) void gemm128(
    const float* __restrict__ A, int lda,
    const float* __restrict__ B, int ldb,
    float* __restrict__ C, int ldc,
    int K, const float* __restrict__ bias)
{
    __shared__ __align__(16) float As[16][132];  // [k][m], padded
    __shared__ __align__(16) float Bs[16][132];  // [k][n], padded
    const int t  = threadIdx.x;
    const int m0 = blockIdx.y * 128;
    const int n0 = blockIdx.x * 128;
    const int tx = t & 15;        // n micro-tile
    const int ty = t >> 4;        // m micro-tile
    const int lr = t >> 2;        // load row 0..63
    const int lk = (t & 3) * 4;   // load k offset 0,4,8,12

    const float* Ab = A + (size_t)m0 * lda;
    const float* Bb = B + (size_t)n0 * ldb;

    float acc[8][8];
    #pragma unroll
    for (int i = 0; i < 8; i++)
        #pragma unroll
        for (int j = 0; j < 8; j++) acc[i][j] = 0.f;

    for (int k0 = 0; k0 < K; k0 += 16) {
        #pragma unroll
        for (int h = 0; h < 2; h++) {
            int r = lr + h * 64;
            float4 va = *(const float4*)(Ab + (size_t)r * lda + k0 + lk);
            As[lk + 0][r] = va.x; As[lk + 1][r] = va.y;
            As[lk + 2][r] = va.z; As[lk + 3][r] = va.w;
            float4 vb = *(const float4*)(Bb + (size_t)r * ldb + k0 + lk);
            Bs[lk + 0][r] = vb.x; Bs[lk + 1][r] = vb.y;
            Bs[lk + 2][r] = vb.z; Bs[lk + 3][r] = vb.w;
        }
        __syncthreads();
        #pragma unroll
        for (int k = 0; k < 16; k++) {
            float4 a0 = *(const float4*)&As[k][ty * 8];
            float4 a1 = *(const float4*)&As[k][ty * 8 + 4];
            float4 b0 = *(const float4*)&Bs[k][tx * 8];
            float4 b1 = *(const float4*)&Bs[k][tx * 8 + 4];
            float a[8]  = {a0.x, a0.y, a0.z, a0.w, a1.x, a1.y, a1.z, a1.w};
            float bv[8] = {b0.x, b0.y, b0.z, b0.w, b1.x, b1.y, b1.z, b1.w};
            #pragma unroll
            for (int i = 0; i < 8; i++)
                #pragma unroll
                for (int j = 0; j < 8; j++)
                    acc[i][j] = fmaf(a[i], bv[j], acc[i][j]);
        }
        __syncthreads();
    }

    #pragma unroll
    for (int i = 0; i < 8; i++) {
        int row = m0 + ty * 8 + i;
        #pragma unroll
        for (int j = 0; j < 8; j++) {
            int col = n0 + tx * 8 + j;
            float v = acc[i][j];
            if (EPI == 1) v = softplusf(v + bias[col]);
            C[(size_t)row * ldc + col] = v;
        }
    }
}

// ============================================================================
// Skinny-N GEMM for x_proj: BM=64, BN=32, BK=32, 256 threads, 4x2 micro-tile.
// N=96 -> 3 N-tiles, M=2048 -> 32 M-tiles = 96 blocks.
// ============================================================================
__global__ __launch_bounds__(256) void gemm_skinny(
    const float* __restrict__ A, int lda,
    const float* __restrict__ B, int ldb,
    float* __restrict__ C, int ldc, int K)
{
    __shared__ float As[32][65];
    __shared__ float Bs[32][33];
    const int t  = threadIdx.x;
    const int m0 = blockIdx.y * 64;
    const int n0 = blockIdx.x * 32;
    const int tx = t & 15;
    const int ty = t >> 4;
    float acc[4][2] = {};
    for (int k0 = 0; k0 < K; k0 += 32) {
        #pragma unroll
        for (int i = 0; i < 8; i++) {
            int idx = t + 256 * i;
            int r = idx >> 5, c = idx & 31;
            As[c][r] = A[(size_t)(m0 + r) * lda + k0 + c];
        }
        #pragma unroll
        for (int i = 0; i < 4; i++) {
            int idx = t + 256 * i;
            int r = idx >> 5, c = idx & 31;
            Bs[c][r] = B[(size_t)(n0 + r) * ldb + k0 + c];
        }
        __syncthreads();
        #pragma unroll
        for (int k = 0; k < 32; k++) {
            float a[4], b[2];
            #pragma unroll
            for (int i = 0; i < 4; i++) a[i] = As[k][ty * 4 + i];
            b[0] = Bs[k][tx * 2]; b[1] = Bs[k][tx * 2 + 1];
            #pragma unroll
            for (int i = 0; i < 4; i++) {
                acc[i][0] = fmaf(a[i], b[0], acc[i][0]);
                acc[i][1] = fmaf(a[i], b[1], acc[i][1]);
            }
        }
        __syncthreads();
    }
    #pragma unroll
    for (int i = 0; i < 4; i++)
        #pragma unroll
        for (int j = 0; j < 2; j++)
            C[(size_t)(m0 + ty * 4 + i) * ldc + n0 + tx * 2 + j] = acc[i][j];
}

// ============================================================================
// Fused causal depthwise conv (k=4) + bias + SiLU.
// Reads xs half of g_xz, writes g_xs. One thread per (token m, channel d).
// ============================================================================
__global__ __launch_bounds__(256) void conv_silu(
    const float* __restrict__ w, const float* __restrict__ bias)
{
    int idx = blockIdx.x * 256 + threadIdx.x;   // 0 .. MT*DI-1
    int d = idx & (DI - 1);
    int m = idx >> 11;                          // DI = 2048 = 2^11
    int l = m & (LL - 1);
    float acc = bias[d];
    const float* wd = w + d * 4;
    #pragma unroll
    for (int k = 0; k < 4; k++) {
        int lp = l - 3 + k;
        if (lp >= 0)
            acc = fmaf(g_xz[(size_t)(m - 3 + k) * (2 * DI) + d], wd[k], acc);
    }
    float sig = 1.f / (1.f + __expf(-acc));
    g_xs[idx] = acc * sig;
}

// ============================================================================
// Selective scan. 16 lanes per (b,d) channel, one lane per state n.
// h[n] = exp(delta*A[d,n])*h[n] + delta*xs*B[l,n];  y = sum_n h[n]*C[l,n]
// Fused epilogue: g_y = (y + D[d]*xs) * z * sigmoid(z)
// Grid: 65536 threads total = 256 blocks x 256.
// ============================================================================
__global__ __launch_bounds__(256) void scan_kernel(
    const float* __restrict__ A_log, const float* __restrict__ Dp)
{
    int tid = blockIdx.x * 256 + threadIdx.x;
    int n  = tid & 15;           // state index
    int hw = tid >> 4;           // channel id 0..4095
    int b  = hw >> 11;           // /2048
    int d  = hw & (DI - 1);

    float Ac = -__expf(A_log[d * DS + n]);
    float Dd = Dp[d];
    float h = 0.f;
    const int mbase = b * LL;
    const float* dbcB = g_dbc + DR + n;        // B_m column for this n
    const float* dbcC = g_dbc + DR + DS + n;   // C_m column for this n

    for (int l = 0; l < LL; l++) {
        int m = mbase + l;
        float dv = g_delta[(size_t)m * DI + d];
        float xv = g_xs[(size_t)m * DI + d];
        float Bv = dbcB[(size_t)m * DBCW];
        float Cv = dbcC[(size_t)m * DBCW];
        float dA = __expf(dv * Ac);
        h = fmaf(dA, h, dv * xv * Bv);
        float s = h * Cv;
        s += __shfl_xor_sync(0xffffffffu, s, 8);
        s += __shfl_xor_sync(0xffffffffu, s, 4);
        s += __shfl_xor_sync(0xffffffffu, s, 2);
        s += __shfl_xor_sync(0xffffffffu, s, 1);
        if (n == 0) {
            float zv = g_xz[(size_t)m * (2 * DI) + DI + d];
            float y = fmaf(Dd, xv, s);
            float sig = 1.f / (1.f + __expf(-zv));
            g_y[(size_t)m * DI + d] = y * zv * sig;
        }
    }
}

// ============================================================================
// Launcher
// ============================================================================
extern "C" void kernel_launch(void* const* d_in, const int* in_sizes, int n_in,
                              void* d_out, int out_size)
{
    const float* x          = (const float*)d_in[0];
    const float* in_proj_w  = (const float*)d_in[1];
    const float* conv_w     = (const float*)d_in[2];
    const float* conv_b     = (const float*)d_in[3];
    const float* x_proj_w   = (const float*)d_in[4];
    const float* dt_proj_w  = (const float*)d_in[5];
    const float* dt_proj_b  = (const float*)d_in[6];
    const float* A_log      = (const float*)d_in[7];
    const float* Dvec       = (const float*)d_in[8];
    const float* out_proj_w = (const float*)d_in[9];
    float* out = (float*)d_out;

    float *xz, *xs, *dbc, *delta, *y;
    cudaGetSymbolAddress((void**)&xz,    g_xz);
    cudaGetSymbolAddress((void**)&xs,    g_xs);
    cudaGetSymbolAddress((void**)&dbc,   g_dbc);
    cudaGetSymbolAddress((void**)&delta, g_delta);
    cudaGetSymbolAddress((void**)&y,     g_y);

    // 1) in_proj: [2048,1024] x [4096,1024]^T -> [2048,4096]
    gemm128<0><<<dim3(2 * DI / 128, MT / 128), 256>>>(
        x, DM, in_proj_w, DM, xz, 2 * DI, DM, nullptr);

    // 2) causal depthwise conv + SiLU -> g_xs [2048,2048]
    conv_silu<<<(MT * DI) / 256, 256>>>(conv_w, conv_b);

    // 3) x_proj: [2048,2048] x [96,2048]^T -> [2048,96]
    gemm_skinny<<<dim3(DBCW / 32, MT / 64), 256>>>(
        xs, DI, x_proj_w, DI, dbc, DBCW, DI);

    // 4) dt_proj + softplus: [2048,64] x [2048,64]^T -> [2048,2048]
    //    A = dbc (first 64 cols), lda = 96
    gemm128<1><<<dim3(DI / 128, MT / 128), 256>>>(
        dbc, DBCW, dt_proj_w, DR, delta, DI, DR, dt_proj_b);

    // 5) selective scan + gating -> g_y [2048,2048]
    scan_kernel<<<(BB * DI * DS) / 256, 256>>>(A_log, Dvec);

    // 6) out_proj: [2048,2048] x [1024,2048]^T -> [2048,1024]
    gemm128<0><<<dim3(DM / 128, MT / 128), 256>>>(
        y, DI, out_proj_w, DI, out, DM, DI, nullptr);
}

// round 3
// speedup vs baseline: 1.3704x; 1.3704x over previous
#include <cuda_runtime.h>
#include <math.h>

#define DM 1024      // d_model
#define DI 2048      // d_inner
#define DS 16        // d_state
#define DR 64        // dt_rank
#define BB 2         // batch
#define LL 1024      // seq len
#define MT 2048      // BB*LL (token count)
#define DBCW 96      // dt_rank + 2*d_state

// ---- scratch (static device allocations; no runtime alloc) ----
__device__ float g_xz[(size_t)MT * 2 * DI];     // in_proj output [MT, 4096]
__device__ float g_xs[(size_t)MT * DI];         // conv+silu output [MT, 2048]
__device__ float g_dbc[(size_t)MT * DBCW];      // x_proj output [MT, 96]
__device__ float g_delta[(size_t)MT * DI];      // softplus(dt) [MT, 2048]
__device__ float g_y[(size_t)MT * DI];          // scan output (pre out_proj)

__device__ __forceinline__ float softplusf(float x) {
    return (x > 20.f) ? x : log1pf(expf(x));
}

__device__ __forceinline__ unsigned f2tf(float f) {
    unsigned u;
    asm("cvt.rna.tf32.f32 %0, %1;" : "=r"(u) : "f"(f));
    return u;
}

__device__ __forceinline__ void mma_tf32(float c[4], const unsigned a[4], const unsigned b[2]) {
    asm("mma.sync.aligned.m16n8k8.row.col.f32.tf32.tf32.f32 "
        "{%0,%1,%2,%3}, {%4,%5,%6,%7}, {%8,%9}, {%0,%1,%2,%3};"
        : "+f"(c[0]), "+f"(c[1]), "+f"(c[2]), "+f"(c[3])
        : "r"(a[0]), "r"(a[1]), "r"(a[2]), "r"(a[3]), "r"(b[0]), "r"(b[1]));
}

__device__ __forceinline__ void cp16(float* smem, const float* g) {
    unsigned s = (unsigned)__cvta_generic_to_shared(smem);
    asm volatile("cp.async.cg.shared.global [%0], [%1], 16;" :: "r"(s), "l"(g));
}

// ============================================================================
// Tensor-core tf32 GEMM: C[M,N] = A[M,K] * B[N,K]^T (row-major, K contiguous)
// Block tile 128 x (NT*32), BK=16, 256 threads (8 warps as 2x4).
// Warp tile 64 x (NT*8): 4 m16 tiles x NT n8 tiles, mma.m16n8k8 tf32.
// Smem row stride 20 floats -> conflict-free fragment loads.
// Double-buffered cp.async pipeline.
// EPI==1: fused C = softplus(C + bias[n]).
// Requires M%128==0, N%(NT*32)==0, K%16==0, rows 16B-aligned.
// ============================================================================
template<int NT, int EPI>
__global__ __launch_bounds__(256) void gemm_mma(
    const float* __restrict__ A, int lda,
    const float* __restrict__ B, int ldb,
    float* __restrict__ C, int ldc,
    int K, const float* __restrict__ bias)
{
    constexpr int BN = NT * 32;
    __shared__ __align__(16) float As[2][128 * 20];
    __shared__ __align__(16) float Bs[2][BN * 20];

    const int t    = threadIdx.x;
    const int wid  = t >> 5;
    const int lane = t & 31;
    const int gid  = lane >> 2;   // 0..7
    const int tig  = lane & 3;    // 0..3
    const int m0   = blockIdx.y * 128;
    const int n0   = blockIdx.x * BN;
    const int wm   = (wid >> 2) * 64;        // warp row offset
    const int wn   = (wid & 3) * (NT * 8);   // warp col offset
    const int lr   = t >> 2;      // 0..63 (load row)
    const int lk   = (t & 3) * 4; // 0,4,8,12 (load k)

    float acc[4][NT][4];
    #pragma unroll
    for (int mi = 0; mi < 4; mi++)
        #pragma unroll
        for (int ni = 0; ni < NT; ni++)
            #pragma unroll
            for (int j = 0; j < 4; j++) acc[mi][ni][j] = 0.f;

    const int niter = K >> 4;

    // issue loads for tile k0 into buffer buf
    auto issue = [&](int buf, int k0) {
        #pragma unroll
        for (int h = 0; h < 2; h++) {
            int r = lr + h * 64;
            cp16(&As[buf][r * 20 + lk], A + (size_t)(m0 + r) * lda + k0 + lk);
        }
        #pragma unroll
        for (int h = 0; h < (BN + 63) / 64; h++) {
            int r = lr + h * 64;
            if ((BN % 64 == 0) || (r < BN))
                cp16(&Bs[buf][r * 20 + lk], B + (size_t)(n0 + r) * ldb + k0 + lk);
        }
        asm volatile("cp.async.commit_group;");
    };

    issue(0, 0);

    for (int it = 0; it < niter; ++it) {
        asm volatile("cp.async.wait_group 0;");
        __syncthreads();
        if (it + 1 < niter) issue((it + 1) & 1, (it + 1) << 4);

        const float* as = As[it & 1];
        const float* bs = Bs[it & 1];

        #pragma unroll
        for (int ks = 0; ks < 2; ks++) {
            const int kb = ks * 8;
            unsigned bf[NT][2];
            #pragma unroll
            for (int ni = 0; ni < NT; ni++) {
                int cb = wn + ni * 8 + gid;
                bf[ni][0] = f2tf(bs[cb * 20 + kb + tig]);
                bf[ni][1] = f2tf(bs[cb * 20 + kb + tig + 4]);
            }
            #pragma unroll
            for (int mi = 0; mi < 4; mi++) {
                int rb = wm + mi * 16 + gid;
                unsigned af[4];
                af[0] = f2tf(as[rb * 20 + kb + tig]);
                af[1] = f2tf(as[(rb + 8) * 20 + kb + tig]);
                af[2] = f2tf(as[rb * 20 + kb + tig + 4]);
                af[3] = f2tf(as[(rb + 8) * 20 + kb + tig + 4]);
                #pragma unroll
                for (int ni = 0; ni < NT; ni++)
                    mma_tf32(acc[mi][ni], af, bf[ni]);
            }
        }
    }

    // epilogue
    #pragma unroll
    for (int mi = 0; mi < 4; mi++) {
        int r0 = m0 + wm + mi * 16 + gid;
        int r1 = r0 + 8;
        #pragma unroll
        for (int ni = 0; ni < NT; ni++) {
            int col = n0 + wn + ni * 8 + tig * 2;
            float v0 = acc[mi][ni][0], v1 = acc[mi][ni][1];
            float v2 = acc[mi][ni][2], v3 = acc[mi][ni][3];
            if (EPI == 1) {
                float b0 = bias[col], b1 = bias[col + 1];
                v0 = softplusf(v0 + b0); v1 = softplusf(v1 + b1);
                v2 = softplusf(v2 + b0); v3 = softplusf(v3 + b1);
            }
            *(float2*)(C + (size_t)r0 * ldc + col) = make_float2(v0, v1);
            *(float2*)(C + (size_t)r1 * ldc + col) = make_float2(v2, v3);
        }
    }
}

// ============================================================================
// Fused causal depthwise conv (k=4) + bias + SiLU.
// Reads xs half of g_xz, writes g_xs. One thread per (token m, channel d).
// ============================================================================
__global__ __launch_bounds__(256) void conv_silu(
    const float* __restrict__ w, const float* __restrict__ bias)
{
    int idx = blockIdx.x * 256 + threadIdx.x;   // 0 .. MT*DI-1
    int d = idx & (DI - 1);
    int m = idx >> 11;                          // DI = 2048 = 2^11
    int l = m & (LL - 1);
    float acc = bias[d];
    const float* wd = w + d * 4;
    #pragma unroll
    for (int k = 0; k < 4; k++) {
        int lp = l - 3 + k;
        if (lp >= 0)
            acc = fmaf(g_xz[(size_t)(m - 3 + k) * (2 * DI) + d], wd[k], acc);
    }
    float sig = 1.f / (1.f + __expf(-acc));
    g_xs[idx] = acc * sig;
}

// ============================================================================
// Selective scan. 16 lanes per (b,d) channel, one lane per state n.
// h[n] = exp(delta*A[d,n])*h[n] + delta*xs*B[l,n];  y = sum_n h[n]*C[l,n]
// Fused epilogue: g_y = (y + D[d]*xs) * z * sigmoid(z)
// ============================================================================
__global__ __launch_bounds__(256) void scan_kernel(
    const float* __restrict__ A_log, const float* __restrict__ Dp)
{
    int tid = blockIdx.x * 256 + threadIdx.x;
    int n  = tid & 15;           // state index
    int hw = tid >> 4;           // channel id 0..4095
    int b  = hw >> 11;           // /2048
    int d  = hw & (DI - 1);

    float Ac = -__expf(A_log[d * DS + n]);
    float Dd = Dp[d];
    float h = 0.f;
    const int mbase = b * LL;
    const float* dbcB = g_dbc + DR + n;        // B_m column for this n
    const float* dbcC = g_dbc + DR + DS + n;   // C_m column for this n

    for (int l = 0; l < LL; l++) {
        int m = mbase + l;
        float dv = g_delta[(size_t)m * DI + d];
        float xv = g_xs[(size_t)m * DI + d];
        float Bv = dbcB[(size_t)m * DBCW];
        float Cv = dbcC[(size_t)m * DBCW];
        float dA = __expf(dv * Ac);
        h = fmaf(dA, h, dv * xv * Bv);
        float s = h * Cv;
        s += __shfl_xor_sync(0xffffffffu, s, 8);
        s += __shfl_xor_sync(0xffffffffu, s, 4);
        s += __shfl_xor_sync(0xffffffffu, s, 2);
        s += __shfl_xor_sync(0xffffffffu, s, 1);
        if (n == 0) {
            float zv = g_xz[(size_t)m * (2 * DI) + DI + d];
            float y = fmaf(Dd, xv, s);
            float sig = 1.f / (1.f + __expf(-zv));
            g_y[(size_t)m * DI + d] = y * zv * sig;
        }
    }
}

// ============================================================================
// Launcher
// ============================================================================
extern "C" void kernel_launch(void* const* d_in, const int* in_sizes, int n_in,
                              void* d_out, int out_size)
{
    const float* x          = (const float*)d_in[0];
    const float* in_proj_w  = (const float*)d_in[1];
    const float* conv_w     = (const float*)d_in[2];
    const float* conv_b     = (const float*)d_in[3];
    const float* x_proj_w   = (const float*)d_in[4];
    const float* dt_proj_w  = (const float*)d_in[5];
    const float* dt_proj_b  = (const float*)d_in[6];
    const float* A_log      = (const float*)d_in[7];
    const float* Dvec       = (const float*)d_in[8];
    const float* out_proj_w = (const float*)d_in[9];
    float* out = (float*)d_out;

    float *xz, *xs, *dbc, *delta, *y;
    cudaGetSymbolAddress((void**)&xz,    g_xz);
    cudaGetSymbolAddress((void**)&xs,    g_xs);
    cudaGetSymbolAddress((void**)&dbc,   g_dbc);
    cudaGetSymbolAddress((void**)&delta, g_delta);
    cudaGetSymbolAddress((void**)&y,     g_y);

    // 1) in_proj: [2048,1024] x [4096,1024]^T -> [2048,4096]
    gemm_mma<4, 0><<<dim3((2 * DI) / 128, MT / 128), 256>>>(
        x, DM, in_proj_w, DM, xz, 2 * DI, DM, nullptr);

    // 2) causal depthwise conv + SiLU -> g_xs [2048,2048]
    conv_silu<<<(MT * DI) / 256, 256>>>(conv_w, conv_b);

    // 3) x_proj: [2048,2048] x [96,2048]^T -> [2048,96]   (BN = 96, one col tile)
    gemm_mma<3, 0><<<dim3(DBCW / 96, MT / 128), 256>>>(
        xs, DI, x_proj_w, DI, dbc, DBCW, DI, nullptr);

    // 4) dt_proj + softplus: [2048,64] x [2048,64]^T -> [2048,2048]
    //    A = dbc (first 64 cols), lda = 96
    gemm_mma<4, 1><<<dim3(DI / 128, MT / 128), 256>>>(
        dbc, DBCW, dt_proj_w, DR, delta, DI, DR, dt_proj_b);

    // 5) selective scan + gating -> g_y [2048,2048]
    scan_kernel<<<(BB * DI * DS) / 256, 256>>>(A_log, Dvec);

    // 6) out_proj: [2048,2048] x [1024,2048]^T -> [2048,1024]
    gemm_mma<4, 0><<<dim3(DM / 128, MT / 128), 256>>>(
        y, DI, out_proj_w, DI, out, DM, DI, nullptr);
}